// round 11
// baseline (speedup 1.0000x reference)
#include <cuda_runtime.h>
#include <cuda_fp16.h>
#include <cstdint>
#include <cstddef>

#define N    8192
#define FIN  512
#define FOUT 256
#define JT     64                 // j per chunk
#define NCHUNK (N / JT)           // 128
#define ITILE  64                 // i rows per CTA
#define NSTAGE 4
#define THREADS 384               // 8 consumer warps + 4 producer warps

// ---------------- scratch (no cudaMalloc allowed) ----------------
__device__ __half g_hT[FOUT * N];             // 4 MB  h^T fp16  [f][i]
__device__ float  g_Wa1[FIN], g_Wa2[FIN];
__device__ float4 g_ivec[N];                  // (-f1, e^{f1}, e^{0.2 f1}, 0)
__device__ float4 g_jvec[N];                  // ( f2, e^{f2}, e^{0.2 f2}, 0)
__device__ int    g_maxbits[2];               // global max of e^{f2}, e^{0.2 f2} (fp32 bits)

typedef unsigned long long ull;

// ---------------- PTX helpers (baseline sm_80+, legal at .target sm_100) ----
__device__ __forceinline__ uint32_t smem_u32(const void* p) {
    uint32_t a;
    asm("{ .reg .u64 t; cvta.to.shared.u64 t, %1; cvt.u32.u64 %0, t; }" : "=r"(a) : "l"(p));
    return a;
}
#define CP_ASYNC16(dst, src) \
    asm volatile("cp.async.cg.shared.global [%0], [%1], 16;" :: "r"((uint32_t)(dst)), "l"(src) : "memory")
#define CP_COMMIT() asm volatile("cp.async.commit_group;" ::: "memory")
#define CP_WAIT0()  asm volatile("cp.async.wait_group 0;" ::: "memory")
#define CP_WAIT1()  asm volatile("cp.async.wait_group 1;" ::: "memory")
#define BAR_SYNC(id)   asm volatile("bar.sync %0, %1;"   :: "r"(id), "r"(THREADS) : "memory")
#define BAR_ARRIVE(id) asm volatile("bar.arrive %0, %1;" :: "r"(id), "r"(THREADS) : "memory")

__device__ __forceinline__ void ldsm4(uint32_t* r, uint32_t addr) {
    asm volatile("ldmatrix.sync.aligned.m8n8.x4.shared.b16 {%0,%1,%2,%3}, [%4];"
        : "=r"(r[0]), "=r"(r[1]), "=r"(r[2]), "=r"(r[3]) : "r"(addr));
}
__device__ __forceinline__ void mmaf16(float* d, const uint32_t* a, uint32_t b0, uint32_t b1) {
    asm volatile("mma.sync.aligned.m16n8k16.row.col.f32.f16.f16.f32 "
        "{%0,%1,%2,%3}, {%4,%5,%6,%7}, {%8,%9}, {%0,%1,%2,%3};"
        : "+f"(d[0]), "+f"(d[1]), "+f"(d[2]), "+f"(d[3])
        : "r"(a[0]), "r"(a[1]), "r"(a[2]), "r"(a[3]), "r"(b0), "r"(b1));
}

__device__ __forceinline__ ull pk2(float lo, float hi) {
    ull r; asm("mov.b64 %0, {%1,%2};" : "=l"(r) : "f"(lo), "f"(hi)); return r;
}
__device__ __forceinline__ void upk2(ull v, float& lo, float& hi) {
    asm("mov.b64 {%0,%1}, %2;" : "=f"(lo), "=f"(hi) : "l"(v));
}
__device__ __forceinline__ ull fma2(ull a, ull b, ull c) {
    ull d; asm("fma.rn.f32x2 %0, %1, %2, %3;" : "=l"(d) : "l"(a), "l"(b), "l"(c)); return d;
}
__device__ __forceinline__ uint32_t sw128(uint32_t off) { return off ^ ((off >> 3) & 0x70); }

// ---------------------------------------------------------------------------
// Kernel 1: Wa1 = W @ a1, Wa2 = W @ a2 (+ init global maxes)
// ---------------------------------------------------------------------------
__global__ void k_wa(const float* __restrict__ W,
                     const float* __restrict__ a1,
                     const float* __restrict__ a2) {
    __shared__ float a1s[FOUT], a2s[FOUT];
    int tid = threadIdx.x;
    if (blockIdx.x == 0 && tid < 2) g_maxbits[tid] = 0;
    if (tid < FOUT) { a1s[tid] = a1[tid]; a2s[tid] = a2[tid]; }
    __syncthreads();
    int warp = tid >> 5, lane = tid & 31;
    int row = blockIdx.x * 8 + warp;
    const float* wr = W + (size_t)row * FOUT;
    float s1 = 0.f, s2 = 0.f;
    for (int c = lane; c < FOUT; c += 32) {
        float w = wr[c];
        s1 += w * a1s[c];
        s2 += w * a2s[c];
    }
    #pragma unroll
    for (int o = 16; o; o >>= 1) {
        s1 += __shfl_down_sync(0xFFFFFFFFu, s1, o);
        s2 += __shfl_down_sync(0xFFFFFFFFu, s2, o);
    }
    if (lane == 0) { g_Wa1[row] = s1; g_Wa2[row] = s2; }
}

// ---------------------------------------------------------------------------
// Kernel 2: exact fp32 logits f1,f2 + factored-exp vectors + global maxes
// ---------------------------------------------------------------------------
__global__ void k_f(const float* __restrict__ X) {
    __shared__ float wa1[FIN], wa2[FIN];
    int tid = threadIdx.x;
    for (int c = tid; c < FIN; c += 256) { wa1[c] = g_Wa1[c]; wa2[c] = g_Wa2[c]; }
    __syncthreads();
    int warp = tid >> 5, lane = tid & 31;
    int row = blockIdx.x * 8 + warp;
    const float* xr = X + (size_t)row * FIN;
    float s1 = 0.f, s2 = 0.f;
    for (int c = lane; c < FIN; c += 32) {
        float x = xr[c];
        s1 += x * wa1[c];
        s2 += x * wa2[c];
    }
    #pragma unroll
    for (int o = 16; o; o >>= 1) {
        s1 += __shfl_down_sync(0xFFFFFFFFu, s1, o);
        s2 += __shfl_down_sync(0xFFFFFFFFu, s2, o);
    }
    if (lane == 0) {
        float e2p = expf(s2), e2n = expf(0.2f * s2);
        g_ivec[row] = make_float4(-s1, expf(s1), expf(0.2f * s1), 0.f);
        g_jvec[row] = make_float4(s2, e2p, e2n, 0.f);
        atomicMax(&g_maxbits[0], __float_as_int(e2p));   // positive floats: int-compare OK
        atomicMax(&g_maxbits[1], __float_as_int(e2n));
    }
}

// ---------------------------------------------------------------------------
// Kernel 3: h = X @ W (fp32), output TRANSPOSED as fp16: g_hT[f][i]
// ---------------------------------------------------------------------------
__global__ __launch_bounds__(256) void k_gemm(const float* __restrict__ X,
                                              const float* __restrict__ W) {
    __shared__ float Xs[64][17];
    __shared__ float Ws[16][64];
    __shared__ float Ts[64][65];
    int tid = threadIdx.x;
    int tx = tid & 15, ty = tid >> 4;
    int i0 = blockIdx.x * 64, n0 = blockIdx.y * 64;

    ull acc[4][2];
    #pragma unroll
    for (int qi = 0; qi < 4; qi++)
        for (int p = 0; p < 2; p++) acc[qi][p] = pk2(0.f, 0.f);

    for (int k0 = 0; k0 < FIN; k0 += 16) {
        {
            int c = tid & 15, r0 = tid >> 4;
            #pragma unroll
            for (int q = 0; q < 4; q++) {
                int r = r0 + 16 * q;
                Xs[r][c] = X[(size_t)(i0 + r) * FIN + k0 + c];
            }
        }
        {
            int c = tid & 63, r0 = tid >> 6;
            #pragma unroll
            for (int q = 0; q < 4; q++) {
                int r = r0 + 4 * q;
                Ws[r][c] = W[(size_t)(k0 + r) * FOUT + n0 + c];
            }
        }
        __syncthreads();
        #pragma unroll
        for (int k = 0; k < 16; k++) {
            float a_[4], b_[4];
            #pragma unroll
            for (int q = 0; q < 4; q++) a_[q] = Xs[ty * 4 + q][k];
            #pragma unroll
            for (int q = 0; q < 4; q++) b_[q] = Ws[k][tx * 4 + q];
            ull b20 = pk2(b_[0], b_[1]);
            ull b21 = pk2(b_[2], b_[3]);
            #pragma unroll
            for (int qi = 0; qi < 4; qi++) {
                ull av = pk2(a_[qi], a_[qi]);
                acc[qi][0] = fma2(av, b20, acc[qi][0]);
                acc[qi][1] = fma2(av, b21, acc[qi][1]);
            }
        }
        __syncthreads();
    }
    #pragma unroll
    for (int qi = 0; qi < 4; qi++) {
        float v0, v1, v2, v3;
        upk2(acc[qi][0], v0, v1);
        upk2(acc[qi][1], v2, v3);
        int il = ty * 4 + qi;
        Ts[tx * 4 + 0][il] = v0;
        Ts[tx * 4 + 1][il] = v1;
        Ts[tx * 4 + 2][il] = v2;
        Ts[tx * 4 + 3][il] = v3;
    }
    __syncthreads();
    {
        int fl = tid >> 2, ib = (tid & 3) * 16;
        __half hb[16];
        #pragma unroll
        for (int k = 0; k < 16; k++) hb[k] = __float2half(Ts[fl][ib + k]);
        size_t base = (size_t)(n0 + fl) * N + i0 + ib;
        *(uint4*)(g_hT + base)     = *(uint4*)&hb[0];
        *(uint4*)(g_hT + base + 8) = *(uint4*)&hb[8];
    }
}

// ---------------------------------------------------------------------------
// Kernel 4: WARP-SPECIALIZED masked-softmax aggregation (fp16 mma.sync).
// grid = 128 i-tiles, 384 threads: warps 0-7 consumers (MMA), 8-11 producers.
// 4-stage ring: A(64x64 w fp16) 8K | jvec 1K | B(256x64 hT fp16) 32K = 41K.
// FULL[s]=bar 1+s, EMPTY[s]=bar 5+s (count=384: arrive+sync mixed).
// Full j-range per CTA -> Z complete in-CTA -> fused normalize+ELU epilogue.
// ---------------------------------------------------------------------------
#define STAGE_B  41984
#define OFF_A(s)  ((s) * STAGE_B)
#define OFF_JV(s) ((s) * STAGE_B + 8192)
#define OFF_B(s)  ((s) * STAGE_B + 9216)
#define SMEM_ATTN (NSTAGE * STAGE_B)   // 167936

__global__ __launch_bounds__(THREADS, 1) void k_attn(const int* __restrict__ adj,
                                                     float* __restrict__ out) {
    extern __shared__ char smem[];
    __shared__ float zs[ITILE];
    const uint32_t sb = smem_u32(smem);
    const int tid = threadIdx.x;
    const int i0 = blockIdx.x * ITILE;
    const int warp = tid >> 5, lane = tid & 31;

    if (warp < 8) {
        // ================= CONSUMERS: 8 warps, MMA only =================
        const int mw = warp >> 2;          // rows [mw*32, mw*32+32)
        const int fw = warp & 3;           // cols [fw*64, fw*64+64)
        const int gr = lane >> 3, lr = lane & 7;
        const int a_rbase = mw * 32 + lr + (gr & 1) * 8;
        const int a_koff = (gr >> 1) * 8;
        const int b_roff = fw * 64 + lr + (gr >> 1) * 8;
        const int b_koff = (gr & 1) * 8;

        float acc[64];
        #pragma unroll
        for (int q = 0; q < 64; q++) acc[q] = 0.f;

        for (int c = 0; c < NCHUNK; c++) {
            const int s = c & (NSTAGE - 1);
            BAR_SYNC(1 + s);               // wait FULL
            const uint32_t aBase = sb + OFF_A(s);
            const uint32_t bBase = sb + OFF_B(s);
            #pragma unroll
            for (int k0 = 0; k0 < JT; k0 += 16) {
                uint32_t A0[4], A1[4];
                uint32_t ao0 = sw128((uint32_t)(a_rbase * 128 + (k0 + a_koff) * 2));
                uint32_t ao1 = sw128((uint32_t)((a_rbase + 16) * 128 + (k0 + a_koff) * 2));
                ldsm4(A0, aBase + ao0);
                ldsm4(A1, aBase + ao1);
                #pragma unroll
                for (int nb = 0; nb < 4; nb++) {
                    uint32_t boff = sw128((uint32_t)((b_roff + nb * 16) * 128 + (k0 + b_koff) * 2));
                    uint32_t Bh[4];
                    ldsm4(Bh, bBase + boff);
                    mmaf16(acc + nb * 8,          A0, Bh[0], Bh[1]);
                    mmaf16(acc + nb * 8 + 4,      A0, Bh[2], Bh[3]);
                    mmaf16(acc + 32 + nb * 8,     A1, Bh[0], Bh[1]);
                    mmaf16(acc + 32 + nb * 8 + 4, A1, Bh[2], Bh[3]);
                }
            }
            BAR_ARRIVE(5 + s);             // signal EMPTY
        }
        __syncthreads();                   // zs ready (producers wrote it)

        // ---- fused epilogue: normalize + ELU, direct to out ----
        const int qr = lane >> 2, qc = lane & 3;
        #pragma unroll
        for (int mt = 0; mt < 2; mt++) {
            int r0 = mw * 32 + mt * 16 + qr;
            float inv0 = 1.f / zs[r0];
            float inv1 = 1.f / zs[r0 + 8];
            float* base0 = out + (size_t)(i0 + r0) * FOUT + fw * 64 + 2 * qc;
            float* base1 = base0 + 8 * FOUT;
            #pragma unroll
            for (int nb = 0; nb < 4; nb++) {
                const float* a = acc + mt * 32 + nb * 8;
                float v;
                float2 o0, o1, o2, o3;
                v = a[0] * inv0; o0.x = (v > 0.f) ? v : expm1f(v);
                v = a[1] * inv0; o0.y = (v > 0.f) ? v : expm1f(v);
                v = a[2] * inv1; o1.x = (v > 0.f) ? v : expm1f(v);
                v = a[3] * inv1; o1.y = (v > 0.f) ? v : expm1f(v);
                v = a[4] * inv0; o2.x = (v > 0.f) ? v : expm1f(v);
                v = a[5] * inv0; o2.y = (v > 0.f) ? v : expm1f(v);
                v = a[6] * inv1; o3.x = (v > 0.f) ? v : expm1f(v);
                v = a[7] * inv1; o3.y = (v > 0.f) ? v : expm1f(v);
                *(float2*)(base0 + nb * 16)     = o0;
                *(float2*)(base1 + nb * 16)     = o1;
                *(float2*)(base0 + nb * 16 + 8) = o2;
                *(float2*)(base1 + nb * 16 + 8) = o3;
            }
        }
    } else {
        // ================= PRODUCERS: 4 warps =================
        const int pt = tid - 256;          // 0..127
        const int il = pt >> 1;            // i row 0..63
        const int jh = (pt & 1) * 32;      // j half within chunk
        float4 iv = g_ivec[i0 + il];
        {   // per-row power-of-2 scale (cancels exactly in num/Z)
            float e2pmax = __int_as_float(g_maxbits[0]);
            float e2nmax = __int_as_float(g_maxbits[1]);
            float bound = fmaxf(iv.y * e2pmax, iv.z * e2nmax);
            int e;
            frexpf(bound, &e);
            float s = ldexpf(1.f, 14 - e);
            iv.y *= s;
            iv.z *= s;
        }
        const int* adjrow = adj + (size_t)(i0 + il) * N + jh;
        float zacc = 0.f;

        auto issueStage = [&](int s, int jglob) {
            // B: rows 2pt, 2pt+1 of hT chunk (8 x 16B each)
            #pragma unroll
            for (int r = 0; r < 2; r++) {
                const __half* src = g_hT + (size_t)(pt * 2 + r) * N + jglob;
                #pragma unroll
                for (int q = 0; q < 8; q++) {
                    uint32_t sw = sw128((uint32_t)((pt * 2 + r) * 128 + q * 16));
                    CP_ASYNC16(sb + OFF_B(s) + sw, src + q * 8);
                }
            }
            // jvec: 64 x 16B by threads 0..63
            if (pt < JT)
                CP_ASYNC16(sb + OFF_JV(s) + pt * 16, g_jvec + jglob + pt);
            CP_COMMIT();
        };
        auto genA = [&](int s, const int4* am4) {
            const int* am = (const int*)am4;
            const float4* jvp = (const float4*)(smem + OFF_JV(s) + jh * 16);
            uint32_t phv[16];
            #pragma unroll
            for (int p = 0; p < 16; p++) {
                float w[2];
                #pragma unroll
                for (int e = 0; e < 2; e++) {
                    int jj = p * 2 + e;
                    float4 jv = jvp[jj];
                    float wv = (jv.x >= iv.x) ? iv.y * jv.y : iv.z * jv.z;
                    w[e] = am[jj] ? wv : 0.f;
                }
                __half2 hh = __floats2half2_rn(w[0], w[1]);
                zacc += __low2float(hh) + __high2float(hh);
                phv[p] = *(uint32_t*)&hh;
            }
            #pragma unroll
            for (int g = 0; g < 4; g++) {
                uint32_t sw = sw128((uint32_t)(il * 128 + (jh + g * 8) * 2));
                *(uint4*)(smem + OFF_A(s) + sw) =
                    make_uint4(phv[g * 4], phv[g * 4 + 1], phv[g * 4 + 2], phv[g * 4 + 3]);
            }
        };

        // prologue: stage chunk 0
        int4 aR[8];
        issueStage(0, 0);
        {
            const int4* ap = (const int4*)(adjrow);
            #pragma unroll
            for (int q = 0; q < 8; q++) aR[q] = ap[q];
        }

        for (int c = 0; c < NCHUNK; c++) {
            const int s = c & (NSTAGE - 1);
            int4 aN[8];
            if (c + 1 < NCHUNK) {
                const int k = c + 1;
                const int s2 = k & (NSTAGE - 1);
                if (k >= NSTAGE) BAR_SYNC(5 + s2);    // wait EMPTY before overwrite
                issueStage(s2, k * JT);
                const int4* ap = (const int4*)(adjrow + k * JT);
                #pragma unroll
                for (int q = 0; q < 8; q++) aN[q] = ap[q];
                CP_WAIT1();                            // group(c) landed
            } else {
                CP_WAIT0();
            }
            genA(s, aR);
            BAR_ARRIVE(1 + s);                         // signal FULL
            #pragma unroll
            for (int q = 0; q < 8; q++) aR[q] = aN[q];
        }

        // Z: pair-reduce (lanes pt, pt^1 share row il)
        zacc += __shfl_xor_sync(0xFFFFFFFFu, zacc, 1);
        if ((pt & 1) == 0) zs[il] = zacc;
        __syncthreads();
    }
}

// ---------------------------------------------------------------------------
extern "C" void kernel_launch(void* const* d_in, const int* in_sizes, int n_in,
                              void* d_out, int out_size) {
    (void)in_sizes; (void)n_in; (void)out_size;
    const float* X   = (const float*)d_in[0];
    const int*   adj = (const int*)d_in[1];
    const float* W   = (const float*)d_in[2];
    const float* a1  = (const float*)d_in[3];
    const float* a2  = (const float*)d_in[4];
    float* out = (float*)d_out;

    cudaFuncSetAttribute(k_attn, cudaFuncAttributeMaxDynamicSharedMemorySize, SMEM_ATTN);

    k_wa<<<FIN / 8, 256>>>(W, a1, a2);
    k_f<<<N / 8, 256>>>(X);
    k_gemm<<<dim3(N / 64, FOUT / 64), 256>>>(X, W);
    k_attn<<<N / ITILE, THREADS, SMEM_ATTN>>>(adj, out);
}